// round 11
// baseline (speedup 1.0000x reference)
#include <cuda_runtime.h>
#include <cuda_bf16.h>
#include <cstdint>

#define B_   4096
#define HID  512
#define NR   32
#define T_   32
#define NLOG 832          // logit cols padded to 13*64 (805 meaningful)
#define BG   32768        // B_*G
#define KTOT 1536         // 3*512 split-bf16 stacking
#define BM   128
#define BN   64
#define KC   64
#define NCHUNK (KTOT / KC)   // 24
#define APAD 72              // smem row length in bf16 (144B, conflict-free ldmatrix)
#define NBUF 4

// ---------------- scratch (device globals: no allocations allowed) ----------------
__device__ __nv_bfloat16 g_Ab[(size_t)B_ * KTOT];      // [m][k]  (hi,hi,lo)
__device__ __nv_bfloat16 g_Bb[(size_t)NLOG * KTOT];    // [n][k]  (hi,lo,hi)
__device__ float g_logits[(size_t)B_ * NLOG];          // z @ W_cat
__device__ float g_Rf[(size_t)BG * NR];                // [bg][r]
__device__ float g_step[(size_t)B_ * T_ * 8 * 8];      // [b][t][g][opw0..3,dd,d1,d2,act]

__device__ __forceinline__ float sigm(float x) {
    return __fdividef(1.f, 1.f + __expf(-x));
}

__device__ __forceinline__ uint32_t s2u(const void* p) {
    uint32_t a;
    asm("{ .reg .u64 t; cvta.to.shared.u64 t, %1; cvt.u32.u64 %0, t; }" : "=r"(a) : "l"(p));
    return a;
}
__device__ __forceinline__ void cpasync16(uint32_t saddr, const void* g) {
    asm volatile("cp.async.cg.shared.global [%0], [%1], 16;" :: "r"(saddr), "l"(g));
}
__device__ __forceinline__ void ldsm4(uint32_t* r, uint32_t addr) {
    asm volatile("ldmatrix.sync.aligned.m8n8.x4.shared.b16 {%0,%1,%2,%3}, [%4];"
                 : "=r"(r[0]), "=r"(r[1]), "=r"(r[2]), "=r"(r[3]) : "r"(addr));
}
__device__ __forceinline__ void mma16816(float* c, const uint32_t* a, const uint32_t* b) {
    asm volatile(
        "mma.sync.aligned.m16n8k16.row.col.f32.bf16.bf16.f32 "
        "{%0,%1,%2,%3}, {%4,%5,%6,%7}, {%8,%9}, {%0,%1,%2,%3};"
        : "+f"(c[0]), "+f"(c[1]), "+f"(c[2]), "+f"(c[3])
        : "r"(a[0]), "r"(a[1]), "r"(a[2]), "r"(a[3]), "r"(b[0]), "r"(b[1]));
}

// ---------------- probe: no-op to shift ncu's captured launch slot onto gemm ----------------
__global__ void probe_kernel() {}

// ---------------- kernel: pack A = [hi(z), hi(z), lo(z)] bf16, [m][k] ----------------
__global__ void pack_a_kernel(const float* __restrict__ Z) {
    int idx = blockIdx.x * blockDim.x + threadIdx.x;     // B_*KTOT
    int m = idx / KTOT, k = idx - m * KTOT;
    __nv_bfloat16 o;
    if (k < 1024) {
        o = __float2bfloat16(Z[(size_t)m * 512 + (k & 511)]);
    } else {
        float v = Z[(size_t)m * 512 + (k - 1024)];
        __nv_bfloat16 hi = __float2bfloat16(v);
        o = __float2bfloat16(v - __bfloat162float(hi));
    }
    g_Ab[idx] = o;
}

// ---------------- kernel: pack B = [hi(W), lo(W), hi(W)] bf16, [n][k] ----------------
__global__ void pack_b_kernel(const float* __restrict__ wR,  const float* __restrict__ wOp,
                              const float* __restrict__ wD,  const float* __restrict__ wS1,
                              const float* __restrict__ wS2, const float* __restrict__ wL) {
    int idx = blockIdx.x * blockDim.x + threadIdx.x;     // NLOG*KTOT
    int n = idx / KTOT, k = idx - n * KTOT;
    int kr = (k < 1024) ? (k & 511) : (k - 1024);
    float v = 0.f;
    if      (n < 256) v = wR [kr * 256 + n];
    else if (n < 320) v = wOp[kr * 64  + (n - 256)];
    else if (n < 480) v = wD [kr * 160 + (n - 320)];
    else if (n < 640) v = wS1[kr * 160 + (n - 480)];
    else if (n < 800) v = wS2[kr * 160 + (n - 640)];
    else if (n < 805) v = wL [kr * 5   + (n - 800)];
    __nv_bfloat16 hi = __float2bfloat16(v);
    __nv_bfloat16 o;
    if (k < 512)       o = hi;
    else if (k < 1024) o = __float2bfloat16(v - __bfloat162float(hi));  // lo
    else               o = hi;
    g_Bb[idx] = o;
}

// ---------------- kernel: mma.sync GEMM, 4-stage cp.async pipeline ----------------
__global__ __launch_bounds__(256) void gemm_mma() {
    extern __shared__ char sm[];
    const int tid  = threadIdx.x;
    const int lane = tid & 31, warp = tid >> 5;
    const int wm = warp & 3, wn = warp >> 2;
    const int bm = blockIdx.y * BM, bn = blockIdx.x * BN;

    const uint32_t ASZ = BM * APAD * 2;          // 18432
    const uint32_t BSZ = BN * APAD * 2;          // 9216
    const uint32_t BBASE = NBUF * ASZ;           // 73728
    const uint32_t sbase = s2u(sm);

    const __nv_bfloat16* Ag = g_Ab + (size_t)bm * KTOT;
    const __nv_bfloat16* Bg = g_Bb + (size_t)bn * KTOT;

    float acc[2][4][4];
#pragma unroll
    for (int mt = 0; mt < 2; mt++)
#pragma unroll
        for (int nt = 0; nt < 4; nt++)
#pragma unroll
            for (int j = 0; j < 4; j++) acc[mt][nt][j] = 0.f;

#define LOAD_CHUNK(c, buf)                                                          \
    {                                                                               \
        _Pragma("unroll")                                                           \
        for (int i = 0; i < 4; i++) {                                               \
            int idx = tid + i * 256, r = idx >> 3, s = idx & 7;                     \
            cpasync16(sbase + (buf) * ASZ + (uint32_t)(r * (APAD * 2) + s * 16),    \
                      Ag + (size_t)r * KTOT + (c) * KC + s * 8);                    \
        }                                                                           \
        _Pragma("unroll")                                                           \
        for (int i = 0; i < 2; i++) {                                               \
            int idx = tid + i * 256, r = idx >> 3, s = idx & 7;                     \
            cpasync16(sbase + BBASE + (buf) * BSZ + (uint32_t)(r * (APAD * 2) + s * 16), \
                      Bg + (size_t)r * KTOT + (c) * KC + s * 8);                    \
        }                                                                           \
    }

    LOAD_CHUNK(0, 0); asm volatile("cp.async.commit_group;");
    LOAD_CHUNK(1, 1); asm volatile("cp.async.commit_group;");
    LOAD_CHUNK(2, 2); asm volatile("cp.async.commit_group;");

    for (int c = 0; c < NCHUNK; c++) {
        asm volatile("cp.async.wait_group 2;");
        __syncthreads();
        if (c + 3 < NCHUNK) LOAD_CHUNK(c + 3, (c + 3) & 3);
        asm volatile("cp.async.commit_group;");

        const int buf = c & 3;
        const uint32_t aB = sbase + buf * ASZ;
        const uint32_t bB = sbase + BBASE + buf * BSZ;
#pragma unroll
        for (int k16 = 0; k16 < 4; k16++) {
            uint32_t afr[2][4];
#pragma unroll
            for (int mt = 0; mt < 2; mt++) {
                int row = wm * 32 + mt * 16 + (lane & 15);
                uint32_t addr = aB + (uint32_t)(row * (APAD * 2) + ((lane >> 4) * 16) + k16 * 32);
                ldsm4(afr[mt], addr);
            }
            uint32_t bfr[4][2];
#pragma unroll
            for (int p = 0; p < 2; p++) {
                int row = wn * 32 + p * 16 + (lane & 7) + ((lane >> 4) * 8);
                uint32_t addr = bB + (uint32_t)(row * (APAD * 2) + (((lane >> 3) & 1) * 16) + k16 * 32);
                uint32_t t4[4];
                ldsm4(t4, addr);
                bfr[p * 2][0] = t4[0]; bfr[p * 2][1] = t4[1];
                bfr[p * 2 + 1][0] = t4[2]; bfr[p * 2 + 1][1] = t4[3];
            }
#pragma unroll
            for (int mt = 0; mt < 2; mt++)
#pragma unroll
                for (int nt = 0; nt < 4; nt++)
                    mma16816(acc[mt][nt], afr[mt], bfr[nt]);
        }
    }

#pragma unroll
    for (int mt = 0; mt < 2; mt++) {
#pragma unroll
        for (int nt = 0; nt < 4; nt++) {
            int row = bm + wm * 32 + mt * 16 + (lane >> 2);
            int col = bn + wn * 32 + nt * 8 + (lane & 3) * 2;
            float* p0 = g_logits + (size_t)row * NLOG + col;
            *(float2*)p0 = make_float2(acc[mt][nt][0], acc[mt][nt][1]);
            float* p1 = g_logits + (size_t)(row + 8) * NLOG + col;
            *(float2*)p1 = make_float2(acc[mt][nt][2], acc[mt][nt][3]);
        }
    }
#undef LOAD_CHUNK
}

// ---------------- kernel: per-step params, exp-sharing across the 8 g's ----------------
// one thread per (b,t); sigmoid(l+dg) = 1/(1 + e^{-l} * e^{-dg}) reuses e^{-l}.
__global__ __launch_bounds__(256) void step_kernel() {
    int idx = blockIdx.x * blockDim.x + threadIdx.x;   // B_*T_ threads, t fastest
    int t = idx & 31;
    int b = idx >> 5;
    const float* row = g_logits + (size_t)b * NLOG;

    float Eop0 = __expf(-row[256 + 2 * t]);
    float Eop1 = __expf(-row[257 + 2 * t]);
    float Ed[5], E1[5], E2[5], El[5];
#pragma unroll
    for (int j = 0; j < 5; j++) {
        Ed[j] = __expf(-row[320 + 5 * t + j]);
        E1[j] = __expf(-row[480 + 5 * t + j]);
        E2[j] = __expf(-row[640 + 5 * t + j]);
        El[j] = __expf(-row[800 + j]);
    }

    float4* outp = (float4*)(g_step + ((size_t)b * 256 + t * 8) * 8);
    const float tm = (float)t + 0.5f;
#pragma unroll
    for (int g = 0; g < 8; g++) {
        float dg = (float)g * (2.f / 7.f) - 1.f;
        float C = __expf(-dg);

        float op_d = __fdividef(1.f, fmaf(Eop0, C, 1.f))
                   + 2.f * __fdividef(1.f, fmaf(Eop1, C, 1.f));
        float dd = 0.f, d1 = 0.f, d2 = 0.f, pl = 0.f;
#pragma unroll
        for (int j = 0; j < 5; j++) {
            float pw = (float)(1 << j);
            dd += __fdividef(1.f, fmaf(Ed[j], C, 1.f)) * pw;
            d1 += __fdividef(1.f, fmaf(E1[j], C, 1.f)) * pw;
            d2 += __fdividef(1.f, fmaf(E2[j], C, 1.f)) * pw;
            pl += __fdividef(1.f, fmaf(El[j], C, 1.f)) * pw;
        }
        float act = sigm(pl - tm);

        float e0 = __expf(-op_d * op_d);
        float p1 = op_d - 1.f; float e1 = __expf(-p1 * p1);
        float p2 = op_d - 2.f; float e2 = __expf(-p2 * p2);
        float p3 = op_d - 3.f; float e3 = __expf(-p3 * p3);
        float inv = __fdividef(1.f, e0 + e1 + e2 + e3);

        outp[g * 2]     = make_float4(e0 * inv, e1 * inv, e2 * inv, e3 * inv);
        outp[g * 2 + 1] = make_float4(dd, d1, d2, act);
    }
}

// ---------------- kernel: 32-step soft-VM scan, 4 lanes per (b,g), R0 fused ----------------
__global__ __launch_bounds__(128) void scan_kernel() {
    const int t4 = blockIdx.x * 128 + threadIdx.x;     // BG*4 threads
    const int bg = t4 >> 2, q = t4 & 3;
    const int b = bg >> 3, g = bg & 7;
    const float dg = (float)g * (2.f / 7.f) - 1.f;
    const int s0 = q * 8;                              // this lane's slots s0..s0+7

    // fused R0: decode this lane's 8 registers from logits
    const float* lr = g_logits + (size_t)b * NLOG + s0 * 8;
    float r[8], m[8];
#pragma unroll
    for (int j = 0; j < 8; j++) {
        float v = 0.f;
#pragma unroll
        for (int jb = 0; jb < 8; jb++)
            v += sigm(lr[j * 8 + jb] + dg) * (float)(1 << jb);
        r[j] = v; m[j] = 0.f;
    }

    const float* sbase = g_step + ((size_t)b * 256 + g) * 8;
    for (int t = 0; t < 32; t++) {
        const float4* sp = (const float4*)(sbase + (size_t)t * 64);
        float4 p0 = sp[0], p1 = sp[1];
        float ow0 = p0.x, ow1 = p0.y, ow2 = p0.z, ow3 = p0.w;
        float dd = p1.x, d1 = p1.y, d2 = p1.z, act = p1.w;

        float ed[8];
        float sd = 0.f, sa = 0.f, sb = 0.f;
        float dv = 0.f, v1 = 0.f, v2 = 0.f, lv = 0.f;
#pragma unroll
        for (int j = 0; j < 8; j++) {
            float fi = (float)(s0 + j);
            float pd = dd - fi; float e_d = __expf(-pd * pd);
            float pa = d1 - fi; float e_1 = __expf(-pa * pa);
            float pb = d2 - fi; float e_2 = __expf(-pb * pb);
            ed[j] = e_d;
            sd += e_d; sa += e_1; sb += e_2;
            dv += r[j] * e_d; v1 += r[j] * e_1; v2 += r[j] * e_2; lv += m[j] * e_1;
        }
#pragma unroll
        for (int off = 1; off <= 2; off <<= 1) {
            sd += __shfl_xor_sync(0xffffffffu, sd, off);
            sa += __shfl_xor_sync(0xffffffffu, sa, off);
            sb += __shfl_xor_sync(0xffffffffu, sb, off);
            dv += __shfl_xor_sync(0xffffffffu, dv, off);
            v1 += __shfl_xor_sync(0xffffffffu, v1, off);
            v2 += __shfl_xor_sync(0xffffffffu, v2, off);
            lv += __shfl_xor_sync(0xffffffffu, lv, off);
        }
        float inv_sd = __fdividef(1.f, sd);
        float inv_sa = __fdividef(1.f, sa);
        float inv_sb = __fdividef(1.f, sb);
        dv *= inv_sd; v1 *= inv_sa; v2 *= inv_sb; lv *= inv_sa;

        float res = ow0 * (v1 + v2) + ow1 * (v1 - v2) + ow2 * lv + ow3 * dv;
        float grs = act * (ow0 + ow1 + ow2) * inv_sd;
        float gms = act * ow3 * inv_sd;
#pragma unroll
        for (int j = 0; j < 8; j++) {
            float w = ed[j];
            float gr = grs * w;
            r[j] += gr * (res - r[j]);
            float gm = gms * w;
            m[j] += gm * (v1 - m[j]);
        }
    }
    float* orow = g_Rf + (size_t)bg * 32 + s0;
    *(float4*)(orow)     = make_float4(r[0], r[1], r[2], r[3]);
    *(float4*)(orow + 4) = make_float4(r[4], r[5], r[6], r[7]);
}

// ---------------- kernel: h = Rf @ W_r2h^T + b, fused LayerNorm ----------------
__global__ __launch_bounds__(512) void final_kernel(const float* __restrict__ Wr,
                                                    const float* __restrict__ bias,
                                                    const float* __restrict__ lng,
                                                    const float* __restrict__ lnb,
                                                    float* __restrict__ out,
                                                    int rows_per_block) {
    const int c = threadIdx.x;
    const int lane = c & 31, warp = c >> 5;

    float w[32];
#pragma unroll
    for (int j = 0; j < 8; j++) {
        float4 v = *(const float4*)(Wr + (size_t)c * 32 + j * 4);
        w[4 * j] = v.x; w[4 * j + 1] = v.y; w[4 * j + 2] = v.z; w[4 * j + 3] = v.w;
    }
    const float bb = bias[c], gg = lng[c], be = lnb[c];

    __shared__ float srf[128];
    __shared__ float red[16][8];
    __shared__ float fin[8];

    const int row_base = blockIdx.x * rows_per_block;
    for (int batch = 0; batch < rows_per_block; batch += 4) {
        const int row0 = row_base + batch;
        __syncthreads();
        if (c < 128)
            srf[c] = g_Rf[(size_t)(row0 + (c & 3)) * 32 + (c >> 2)];
        __syncthreads();

        float a0 = 0.f, a1 = 0.f, a2 = 0.f, a3 = 0.f;
#pragma unroll
        for (int rIdx = 0; rIdx < 32; rIdx++) {
            float4 v = *(const float4*)&srf[rIdx * 4];
            float ww = w[rIdx];
            a0 += ww * v.x; a1 += ww * v.y; a2 += ww * v.z; a3 += ww * v.w;
        }
        float h[4] = {a0 + bb, a1 + bb, a2 + bb, a3 + bb};

        float s[8];
#pragma unroll
        for (int j = 0; j < 4; j++) { s[j] = h[j]; s[4 + j] = h[j] * h[j]; }
#pragma unroll
        for (int off = 16; off > 0; off >>= 1)
#pragma unroll
            for (int j = 0; j < 8; j++) s[j] += __shfl_xor_sync(0xffffffffu, s[j], off);
        if (lane == 0)
#pragma unroll
            for (int j = 0; j < 8; j++) red[warp][j] = s[j];
        __syncthreads();
        if (c < 8) {
            float tot = 0.f;
#pragma unroll
            for (int wi = 0; wi < 16; wi++) tot += red[wi][c];
            fin[c] = tot;
        }
        __syncthreads();
#pragma unroll
        for (int rr = 0; rr < 4; rr++) {
            float mu  = fin[rr] * (1.f / 512.f);
            float msq = fin[4 + rr] * (1.f / 512.f);
            float var = msq - mu * mu;
            float sc  = rsqrtf(var + 1e-5f);
            out[(size_t)(row0 + rr) * 512 + c] = (h[rr] - mu) * sc * gg + be;
        }
    }
}

// ---------------- launch ----------------
extern "C" void kernel_launch(void* const* d_in, const int* in_sizes, int n_in,
                              void* d_out, int out_size) {
    const float* z    = (const float*)d_in[0];
    const float* wR   = (const float*)d_in[1];
    const float* wOp  = (const float*)d_in[2];
    const float* wD   = (const float*)d_in[3];
    const float* wS1  = (const float*)d_in[4];
    const float* wS2  = (const float*)d_in[5];
    const float* wL   = (const float*)d_in[6];
    const float* wr2h = (const float*)d_in[7];
    const float* br2h = (const float*)d_in[8];
    const float* lng  = (const float*)d_in[9];
    const float* lnb  = (const float*)d_in[10];
    float* out = (float*)d_out;

    const int GEMM_SMEM = NBUF * (BM + BN) * APAD * 2;   // 110592 bytes
    cudaFuncSetAttribute(gemm_mma, cudaFuncAttributeMaxDynamicSharedMemorySize, GEMM_SMEM);

    pack_a_kernel<<<(B_ * KTOT) / 256, 256>>>(z);                       // launch 1
    pack_b_kernel<<<(NLOG * KTOT) / 256, 256>>>(wR, wOp, wD, wS1, wS2, wL); // 2
    probe_kernel<<<1, 32>>>();                                          // 3 (shifts ncu slot)
    gemm_mma<<<dim3(NLOG / BN, B_ / BM), 256, GEMM_SMEM>>>();           // 4 <- profiled
    step_kernel<<<(B_ * T_) / 256, 256>>>();                            // 5
    scan_kernel<<<(BG * 4) / 128, 128>>>();                             // 6
    final_kernel<<<1024, 512>>>(wr2h, br2h, lng, lnb, out, BG / 1024);  // 7
}

// round 13
// speedup vs baseline: 1.0464x; 1.0464x over previous
#include <cuda_runtime.h>
#include <cuda_bf16.h>
#include <cstdint>

#define B_   4096
#define HID  512
#define NR   32
#define T_   32
#define NLOG 832          // logit cols padded to 13*64 (805 meaningful)
#define BG   32768        // B_*G
#define KTOT 1536         // 3*512 split-bf16 stacking
#define BM   128
#define BN   64
#define KC   64
#define NCHUNK (KTOT / KC)   // 24
#define APAD 72              // smem row length in bf16 (144B, conflict-free ldmatrix)
#define NBUF 4
#define ANUM (B_ * KTOT)     // 6291456 = 24576 blocks * 256

// ---------------- scratch (device globals: no allocations allowed) ----------------
__device__ __nv_bfloat16 g_Ab[(size_t)B_ * KTOT];      // [m][k]  (hi,hi,lo)
__device__ __nv_bfloat16 g_Bb[(size_t)NLOG * KTOT];    // [n][k]  (hi,lo,hi)
__device__ float g_logits[(size_t)B_ * NLOG];          // z @ W_cat
__device__ float g_Rf[(size_t)BG * NR];                // [bg][r]

__device__ __forceinline__ float sigm(float x) {
    return __fdividef(1.f, 1.f + __expf(-x));
}

__device__ __forceinline__ uint32_t s2u(const void* p) {
    uint32_t a;
    asm("{ .reg .u64 t; cvta.to.shared.u64 t, %1; cvt.u32.u64 %0, t; }" : "=r"(a) : "l"(p));
    return a;
}
__device__ __forceinline__ void cpasync16(uint32_t saddr, const void* g) {
    asm volatile("cp.async.cg.shared.global [%0], [%1], 16;" :: "r"(saddr), "l"(g));
}
__device__ __forceinline__ void ldsm4(uint32_t* r, uint32_t addr) {
    asm volatile("ldmatrix.sync.aligned.m8n8.x4.shared.b16 {%0,%1,%2,%3}, [%4];"
                 : "=r"(r[0]), "=r"(r[1]), "=r"(r[2]), "=r"(r[3]) : "r"(addr));
}
__device__ __forceinline__ void mma16816(float* c, const uint32_t* a, const uint32_t* b) {
    asm volatile(
        "mma.sync.aligned.m16n8k16.row.col.f32.bf16.bf16.f32 "
        "{%0,%1,%2,%3}, {%4,%5,%6,%7}, {%8,%9}, {%0,%1,%2,%3};"
        : "+f"(c[0]), "+f"(c[1]), "+f"(c[2]), "+f"(c[3])
        : "r"(a[0]), "r"(a[1]), "r"(a[2]), "r"(a[3]), "r"(b[0]), "r"(b[1]));
}

// ---------------- probe: no-op to place the fused scan at ncu's capture slot ----------------
__global__ void probe_kernel() {}

// ---------------- kernel: fused pack of A and B (block-aligned split) ----------------
__global__ void pack_ab_kernel(const float* __restrict__ Z,
                               const float* __restrict__ wR,  const float* __restrict__ wOp,
                               const float* __restrict__ wD,  const float* __restrict__ wS1,
                               const float* __restrict__ wS2, const float* __restrict__ wL) {
    int idx = blockIdx.x * blockDim.x + threadIdx.x;
    if (idx < ANUM) {                     // A = [hi(z), hi(z), lo(z)], [m][k]
        int m = idx / KTOT, k = idx - m * KTOT;
        __nv_bfloat16 o;
        if (k < 1024) {
            o = __float2bfloat16(Z[(size_t)m * 512 + (k & 511)]);
        } else {
            float v = Z[(size_t)m * 512 + (k - 1024)];
            __nv_bfloat16 hi = __float2bfloat16(v);
            o = __float2bfloat16(v - __bfloat162float(hi));
        }
        g_Ab[idx] = o;
    } else {                              // B = [hi(W), lo(W), hi(W)], [n][k]
        idx -= ANUM;
        int n = idx / KTOT, k = idx - n * KTOT;
        int kr = (k < 1024) ? (k & 511) : (k - 1024);
        float v = 0.f;
        if      (n < 256) v = wR [kr * 256 + n];
        else if (n < 320) v = wOp[kr * 64  + (n - 256)];
        else if (n < 480) v = wD [kr * 160 + (n - 320)];
        else if (n < 640) v = wS1[kr * 160 + (n - 480)];
        else if (n < 800) v = wS2[kr * 160 + (n - 640)];
        else if (n < 805) v = wL [kr * 5   + (n - 800)];
        __nv_bfloat16 hi = __float2bfloat16(v);
        __nv_bfloat16 o;
        if (k < 512)       o = hi;
        else if (k < 1024) o = __float2bfloat16(v - __bfloat162float(hi));  // lo
        else               o = hi;
        g_Bb[idx] = o;
    }
}

// ---------------- kernel: mma.sync GEMM, 4-stage cp.async pipeline ----------------
__global__ __launch_bounds__(256) void gemm_mma() {
    extern __shared__ char sm[];
    const int tid  = threadIdx.x;
    const int lane = tid & 31, warp = tid >> 5;
    const int wm = warp & 3, wn = warp >> 2;
    const int bm = blockIdx.y * BM, bn = blockIdx.x * BN;

    const uint32_t ASZ = BM * APAD * 2;          // 18432
    const uint32_t BSZ = BN * APAD * 2;          // 9216
    const uint32_t BBASE = NBUF * ASZ;           // 73728
    const uint32_t sbase = s2u(sm);

    const __nv_bfloat16* Ag = g_Ab + (size_t)bm * KTOT;
    const __nv_bfloat16* Bg = g_Bb + (size_t)bn * KTOT;

    float acc[2][4][4];
#pragma unroll
    for (int mt = 0; mt < 2; mt++)
#pragma unroll
        for (int nt = 0; nt < 4; nt++)
#pragma unroll
            for (int j = 0; j < 4; j++) acc[mt][nt][j] = 0.f;

#define LOAD_CHUNK(c, buf)                                                          \
    {                                                                               \
        _Pragma("unroll")                                                           \
        for (int i = 0; i < 4; i++) {                                               \
            int idx = tid + i * 256, r = idx >> 3, s = idx & 7;                     \
            cpasync16(sbase + (buf) * ASZ + (uint32_t)(r * (APAD * 2) + s * 16),    \
                      Ag + (size_t)r * KTOT + (c) * KC + s * 8);                    \
        }                                                                           \
        _Pragma("unroll")                                                           \
        for (int i = 0; i < 2; i++) {                                               \
            int idx = tid + i * 256, r = idx >> 3, s = idx & 7;                     \
            cpasync16(sbase + BBASE + (buf) * BSZ + (uint32_t)(r * (APAD * 2) + s * 16), \
                      Bg + (size_t)r * KTOT + (c) * KC + s * 8);                    \
        }                                                                           \
    }

    LOAD_CHUNK(0, 0); asm volatile("cp.async.commit_group;");
    LOAD_CHUNK(1, 1); asm volatile("cp.async.commit_group;");
    LOAD_CHUNK(2, 2); asm volatile("cp.async.commit_group;");

    for (int c = 0; c < NCHUNK; c++) {
        asm volatile("cp.async.wait_group 2;");
        __syncthreads();
        if (c + 3 < NCHUNK) LOAD_CHUNK(c + 3, (c + 3) & 3);
        asm volatile("cp.async.commit_group;");

        const int buf = c & 3;
        const uint32_t aB = sbase + buf * ASZ;
        const uint32_t bB = sbase + BBASE + buf * BSZ;
#pragma unroll
        for (int k16 = 0; k16 < 4; k16++) {
            uint32_t afr[2][4];
#pragma unroll
            for (int mt = 0; mt < 2; mt++) {
                int row = wm * 32 + mt * 16 + (lane & 15);
                uint32_t addr = aB + (uint32_t)(row * (APAD * 2) + ((lane >> 4) * 16) + k16 * 32);
                ldsm4(afr[mt], addr);
            }
            uint32_t bfr[4][2];
#pragma unroll
            for (int p = 0; p < 2; p++) {
                int row = wn * 32 + p * 16 + (lane & 7) + ((lane >> 4) * 8);
                uint32_t addr = bB + (uint32_t)(row * (APAD * 2) + (((lane >> 3) & 1) * 16) + k16 * 32);
                uint32_t t4[4];
                ldsm4(t4, addr);
                bfr[p * 2][0] = t4[0]; bfr[p * 2][1] = t4[1];
                bfr[p * 2 + 1][0] = t4[2]; bfr[p * 2 + 1][1] = t4[3];
            }
#pragma unroll
            for (int mt = 0; mt < 2; mt++)
#pragma unroll
                for (int nt = 0; nt < 4; nt++)
                    mma16816(acc[mt][nt], afr[mt], bfr[nt]);
        }
    }

#pragma unroll
    for (int mt = 0; mt < 2; mt++) {
#pragma unroll
        for (int nt = 0; nt < 4; nt++) {
            int row = bm + wm * 32 + mt * 16 + (lane >> 2);
            int col = bn + wn * 32 + nt * 8 + (lane & 3) * 2;
            float* p0 = g_logits + (size_t)row * NLOG + col;
            *(float2*)p0 = make_float2(acc[mt][nt][0], acc[mt][nt][1]);
            float* p1 = g_logits + (size_t)(row + 8) * NLOG + col;
            *(float2*)p1 = make_float2(acc[mt][nt][2], acc[mt][nt][3]);
        }
    }
#undef LOAD_CHUNK
}

// ---------------- kernel: fused step+scan soft-VM ----------------
// 128 threads/block = 4 warps; warp = one b (8 g x 4 q lanes); lane: g = lane>>2, q = lane&3.
// Per step, lane role q in {0,1,2} decodes dst/src1/src2 (dec5), q=3 decodes op + softmax;
// quad shfls broadcast params; all lanes handle 8 register slots each.
__global__ __launch_bounds__(128) void scan_kernel() {
    __shared__ float slog[4][552];                 // logits[256..805) per warp's b
    const int tid = threadIdx.x;
    const int warp = tid >> 5, lane = tid & 31;
    const int b = blockIdx.x * 4 + warp;
    const int g = lane >> 2, q = lane & 3;
    const float dg = (float)g * (2.f / 7.f) - 1.f;
    const int s0 = q * 8;

    {
        const int bb = blockIdx.x * 4;
        for (int i = tid; i < 4 * 552; i += 128) {
            int bl = i / 552, j = i - bl * 552;
            slog[bl][j] = (j < 549) ? g_logits[(size_t)(bb + bl) * NLOG + 256 + j] : 0.f;
        }
    }
    __syncthreads();
    const float* sl = slog[warp];

    // R0: decode this lane's 8 register slots from logit bits [0..255]
    const float* lr = g_logits + (size_t)b * NLOG + s0 * 8;
    float r[8], m[8];
#pragma unroll
    for (int j = 0; j < 8; j++) {
        float v = 0.f;
#pragma unroll
        for (int jb = 0; jb < 8; jb++)
            v += sigm(lr[j * 8 + jb] + dg) * (float)(1 << jb);
        r[j] = v; m[j] = 0.f;
    }

    // plen (len logits at local 544..548), same for all q of a g
    float pl = 0.f;
#pragma unroll
    for (int j = 0; j < 5; j++) pl += sigm(sl[544 + j] + dg) * (float)(1 << j);

    // role-dependent decode weights/base: q<3 -> dec5 at {64,224,384}+5t; q=3 -> op at 2t w/ weights {1,2,0,0,0}
    float wts[5];
#pragma unroll
    for (int j = 0; j < 5; j++) wts[j] = (q == 3) ? (j == 0 ? 1.f : (j == 1 ? 2.f : 0.f))
                                                  : (float)(1 << j);
    const int boff = (q == 3) ? 0 : (64 + q * 160);
    const int mult = (q == 3) ? 2 : 5;

    for (int t = 0; t < 32; t++) {
        const int ib = boff + mult * t;
        float dec = 0.f;
#pragma unroll
        for (int j = 0; j < 5; j++) dec += wts[j] * sigm(sl[ib + j] + dg);

        float ow0 = 0.f, ow1 = 0.f, ow2 = 0.f, ow3 = 0.f;
        if (q == 3) {                              // op softmax on the q=3 lane only
            float e0 = __expf(-dec * dec);
            float p1 = dec - 1.f; float e1 = __expf(-p1 * p1);
            float p2 = dec - 2.f; float e2 = __expf(-p2 * p2);
            float p3 = dec - 3.f; float e3 = __expf(-p3 * p3);
            float inv = __fdividef(1.f, e0 + e1 + e2 + e3);
            ow0 = e0 * inv; ow1 = e1 * inv; ow2 = e2 * inv; ow3 = e3 * inv;
        }
        const int qb = lane & ~3;
        float dd = __shfl_sync(0xffffffffu, dec, qb);
        float d1 = __shfl_sync(0xffffffffu, dec, qb | 1);
        float d2 = __shfl_sync(0xffffffffu, dec, qb | 2);
        ow0 = __shfl_sync(0xffffffffu, ow0, qb | 3);
        ow1 = __shfl_sync(0xffffffffu, ow1, qb | 3);
        ow2 = __shfl_sync(0xffffffffu, ow2, qb | 3);
        ow3 = __shfl_sync(0xffffffffu, ow3, qb | 3);
        float act = sigm(pl - (float)t - 0.5f);

        float ed[8];
        float sd = 0.f, sa = 0.f, sb = 0.f;
        float dv = 0.f, v1 = 0.f, v2 = 0.f, lv = 0.f;
#pragma unroll
        for (int j = 0; j < 8; j++) {
            float fi = (float)(s0 + j);
            float pd = dd - fi; float e_d = __expf(-pd * pd);
            float pa = d1 - fi; float e_1 = __expf(-pa * pa);
            float pb = d2 - fi; float e_2 = __expf(-pb * pb);
            ed[j] = e_d;
            sd += e_d; sa += e_1; sb += e_2;
            dv += r[j] * e_d; v1 += r[j] * e_1; v2 += r[j] * e_2; lv += m[j] * e_1;
        }
#pragma unroll
        for (int off = 1; off <= 2; off <<= 1) {
            sd += __shfl_xor_sync(0xffffffffu, sd, off);
            sa += __shfl_xor_sync(0xffffffffu, sa, off);
            sb += __shfl_xor_sync(0xffffffffu, sb, off);
            dv += __shfl_xor_sync(0xffffffffu, dv, off);
            v1 += __shfl_xor_sync(0xffffffffu, v1, off);
            v2 += __shfl_xor_sync(0xffffffffu, v2, off);
            lv += __shfl_xor_sync(0xffffffffu, lv, off);
        }
        float inv_sd = __fdividef(1.f, sd);
        float inv_sa = __fdividef(1.f, sa);
        float inv_sb = __fdividef(1.f, sb);
        dv *= inv_sd; v1 *= inv_sa; v2 *= inv_sb; lv *= inv_sa;

        float res = ow0 * (v1 + v2) + ow1 * (v1 - v2) + ow2 * lv + ow3 * dv;
        float grs = act * (ow0 + ow1 + ow2) * inv_sd;
        float gms = act * ow3 * inv_sd;
#pragma unroll
        for (int j = 0; j < 8; j++) {
            float w = ed[j];
            float gr = grs * w;
            r[j] += gr * (res - r[j]);
            float gm = gms * w;
            m[j] += gm * (v1 - m[j]);
        }
    }
    const int bg = b * 8 + g;
    float* orow = g_Rf + (size_t)bg * 32 + s0;
    *(float4*)(orow)     = make_float4(r[0], r[1], r[2], r[3]);
    *(float4*)(orow + 4) = make_float4(r[4], r[5], r[6], r[7]);
}

// ---------------- kernel: h = Rf @ W_r2h^T + b, fused LayerNorm ----------------
__global__ __launch_bounds__(512) void final_kernel(const float* __restrict__ Wr,
                                                    const float* __restrict__ bias,
                                                    const float* __restrict__ lng,
                                                    const float* __restrict__ lnb,
                                                    float* __restrict__ out,
                                                    int rows_per_block) {
    const int c = threadIdx.x;
    const int lane = c & 31, warp = c >> 5;

    float w[32];
#pragma unroll
    for (int j = 0; j < 8; j++) {
        float4 v = *(const float4*)(Wr + (size_t)c * 32 + j * 4);
        w[4 * j] = v.x; w[4 * j + 1] = v.y; w[4 * j + 2] = v.z; w[4 * j + 3] = v.w;
    }
    const float bb = bias[c], gg = lng[c], be = lnb[c];

    __shared__ float srf[128];
    __shared__ float red[16][8];
    __shared__ float fin[8];

    const int row_base = blockIdx.x * rows_per_block;
    for (int batch = 0; batch < rows_per_block; batch += 4) {
        const int row0 = row_base + batch;
        __syncthreads();
        if (c < 128)
            srf[c] = g_Rf[(size_t)(row0 + (c & 3)) * 32 + (c >> 2)];
        __syncthreads();

        float a0 = 0.f, a1 = 0.f, a2 = 0.f, a3 = 0.f;
#pragma unroll
        for (int rIdx = 0; rIdx < 32; rIdx++) {
            float4 v = *(const float4*)&srf[rIdx * 4];
            float ww = w[rIdx];
            a0 += ww * v.x; a1 += ww * v.y; a2 += ww * v.z; a3 += ww * v.w;
        }
        float h[4] = {a0 + bb, a1 + bb, a2 + bb, a3 + bb};

        float s[8];
#pragma unroll
        for (int j = 0; j < 4; j++) { s[j] = h[j]; s[4 + j] = h[j] * h[j]; }
#pragma unroll
        for (int off = 16; off > 0; off >>= 1)
#pragma unroll
            for (int j = 0; j < 8; j++) s[j] += __shfl_xor_sync(0xffffffffu, s[j], off);
        if (lane == 0)
#pragma unroll
            for (int j = 0; j < 8; j++) red[warp][j] = s[j];
        __syncthreads();
        if (c < 8) {
            float tot = 0.f;
#pragma unroll
            for (int wi = 0; wi < 16; wi++) tot += red[wi][c];
            fin[c] = tot;
        }
        __syncthreads();
#pragma unroll
        for (int rr = 0; rr < 4; rr++) {
            float mu  = fin[rr] * (1.f / 512.f);
            float msq = fin[4 + rr] * (1.f / 512.f);
            float var = msq - mu * mu;
            float sc  = rsqrtf(var + 1e-5f);
            out[(size_t)(row0 + rr) * 512 + c] = (h[rr] - mu) * sc * gg + be;
        }
    }
}

// ---------------- launch ----------------
extern "C" void kernel_launch(void* const* d_in, const int* in_sizes, int n_in,
                              void* d_out, int out_size) {
    const float* z    = (const float*)d_in[0];
    const float* wR   = (const float*)d_in[1];
    const float* wOp  = (const float*)d_in[2];
    const float* wD   = (const float*)d_in[3];
    const float* wS1  = (const float*)d_in[4];
    const float* wS2  = (const float*)d_in[5];
    const float* wL   = (const float*)d_in[6];
    const float* wr2h = (const float*)d_in[7];
    const float* br2h = (const float*)d_in[8];
    const float* lng  = (const float*)d_in[9];
    const float* lnb  = (const float*)d_in[10];
    float* out = (float*)d_out;

    const int GEMM_SMEM = NBUF * (BM + BN) * APAD * 2;   // 110592 bytes
    cudaFuncSetAttribute(gemm_mma, cudaFuncAttributeMaxDynamicSharedMemorySize, GEMM_SMEM);

    const int PACK_TOTAL = ANUM + NLOG * KTOT;
    pack_ab_kernel<<<PACK_TOTAL / 256, 256>>>(z, wR, wOp, wD, wS1, wS2, wL);  // 1
    gemm_mma<<<dim3(NLOG / BN, B_ / BM), 256, GEMM_SMEM>>>();                 // 2
    probe_kernel<<<1, 32>>>();                                                // 3
    scan_kernel<<<B_ / 4, 128>>>();                                           // 4 <- profiled
    final_kernel<<<1024, 512>>>(wr2h, br2h, lng, lnb, out, BG / 1024);        // 5
}

// round 15
// speedup vs baseline: 1.1048x; 1.0558x over previous
#include <cuda_runtime.h>
#include <cuda_bf16.h>
#include <cstdint>

#define B_   4096
#define HID  512
#define NR   32
#define T_   32
#define NLOG 832          // logit cols padded to 13*64 (805 meaningful)
#define BG   32768        // B_*G
#define KTOT 1536         // 3*512 split-bf16 stacking
#define BM   128
#define BN   64
#define KC   64
#define NCHUNK (KTOT / KC)   // 24
#define APAD 72              // smem row length in bf16 (144B, conflict-free ldmatrix)
#define NBUF 4
#define ANUM (B_ * KTOT)     // 6291456
#define L2E  1.4426950408889634f
#define SQL  1.2011224087864498f   // sqrt(log2 e)

// ---------------- scratch (device globals: no allocations allowed) ----------------
__device__ __nv_bfloat16 g_Ab[(size_t)B_ * KTOT];      // [m][k]  (hi,hi,lo)
__device__ __nv_bfloat16 g_Bb[(size_t)NLOG * KTOT];    // [n][k]  (hi,lo,hi)
__device__ float g_logits[(size_t)B_ * NLOG];          // z @ W_cat
__device__ float g_Rf[(size_t)BG * NR];                // [bg][r]

__device__ __forceinline__ float sigm(float x) {
    return __fdividef(1.f, 1.f + __expf(-x));
}
__device__ __forceinline__ float ex2f(float x) {
    float y; asm("ex2.approx.ftz.f32 %0, %1;" : "=f"(y) : "f"(x)); return y;
}
__device__ __forceinline__ float rcpf(float x) {
    float y; asm("rcp.approx.ftz.f32 %0, %1;" : "=f"(y) : "f"(x)); return y;
}

__device__ __forceinline__ uint32_t s2u(const void* p) {
    uint32_t a;
    asm("{ .reg .u64 t; cvta.to.shared.u64 t, %1; cvt.u32.u64 %0, t; }" : "=r"(a) : "l"(p));
    return a;
}
__device__ __forceinline__ void cpasync16(uint32_t saddr, const void* g) {
    asm volatile("cp.async.cg.shared.global [%0], [%1], 16;" :: "r"(saddr), "l"(g));
}
__device__ __forceinline__ void ldsm4(uint32_t* r, uint32_t addr) {
    asm volatile("ldmatrix.sync.aligned.m8n8.x4.shared.b16 {%0,%1,%2,%3}, [%4];"
                 : "=r"(r[0]), "=r"(r[1]), "=r"(r[2]), "=r"(r[3]) : "r"(addr));
}
__device__ __forceinline__ void mma16816(float* c, const uint32_t* a, const uint32_t* b) {
    asm volatile(
        "mma.sync.aligned.m16n8k16.row.col.f32.bf16.bf16.f32 "
        "{%0,%1,%2,%3}, {%4,%5,%6,%7}, {%8,%9}, {%0,%1,%2,%3};"
        : "+f"(c[0]), "+f"(c[1]), "+f"(c[2]), "+f"(c[3])
        : "r"(a[0]), "r"(a[1]), "r"(a[2]), "r"(a[3]), "r"(b[0]), "r"(b[1]));
}

// ---------------- kernel: fused pack of A and B (block-aligned split) ----------------
__global__ void pack_ab_kernel(const float* __restrict__ Z,
                               const float* __restrict__ wR,  const float* __restrict__ wOp,
                               const float* __restrict__ wD,  const float* __restrict__ wS1,
                               const float* __restrict__ wS2, const float* __restrict__ wL) {
    int idx = blockIdx.x * blockDim.x + threadIdx.x;
    if (idx < ANUM) {                     // A = [hi(z), hi(z), lo(z)], [m][k]
        int m = idx / KTOT, k = idx - m * KTOT;
        __nv_bfloat16 o;
        if (k < 1024) {
            o = __float2bfloat16(Z[(size_t)m * 512 + (k & 511)]);
        } else {
            float v = Z[(size_t)m * 512 + (k - 1024)];
            __nv_bfloat16 hi = __float2bfloat16(v);
            o = __float2bfloat16(v - __bfloat162float(hi));
        }
        g_Ab[idx] = o;
    } else {                              // B = [hi(W), lo(W), hi(W)], [n][k]
        idx -= ANUM;
        int n = idx / KTOT, k = idx - n * KTOT;
        int kr = (k < 1024) ? (k & 511) : (k - 1024);
        float v = 0.f;
        if      (n < 256) v = wR [kr * 256 + n];
        else if (n < 320) v = wOp[kr * 64  + (n - 256)];
        else if (n < 480) v = wD [kr * 160 + (n - 320)];
        else if (n < 640) v = wS1[kr * 160 + (n - 480)];
        else if (n < 800) v = wS2[kr * 160 + (n - 640)];
        else if (n < 805) v = wL [kr * 5   + (n - 800)];
        __nv_bfloat16 hi = __float2bfloat16(v);
        __nv_bfloat16 o;
        if (k < 512)       o = hi;
        else if (k < 1024) o = __float2bfloat16(v - __bfloat162float(hi));  // lo
        else               o = hi;
        g_Bb[idx] = o;
    }
}

// ---------------- kernel: mma.sync GEMM, 4-stage cp.async pipeline ----------------
__global__ __launch_bounds__(256) void gemm_mma() {
    extern __shared__ char sm[];
    const int tid  = threadIdx.x;
    const int lane = tid & 31, warp = tid >> 5;
    const int wm = warp & 3, wn = warp >> 2;
    const int bm = blockIdx.y * BM, bn = blockIdx.x * BN;

    const uint32_t ASZ = BM * APAD * 2;          // 18432
    const uint32_t BSZ = BN * APAD * 2;          // 9216
    const uint32_t BBASE = NBUF * ASZ;           // 73728
    const uint32_t sbase = s2u(sm);

    const __nv_bfloat16* Ag = g_Ab + (size_t)bm * KTOT;
    const __nv_bfloat16* Bg = g_Bb + (size_t)bn * KTOT;

    float acc[2][4][4];
#pragma unroll
    for (int mt = 0; mt < 2; mt++)
#pragma unroll
        for (int nt = 0; nt < 4; nt++)
#pragma unroll
            for (int j = 0; j < 4; j++) acc[mt][nt][j] = 0.f;

#define LOAD_CHUNK(c, buf)                                                          \
    {                                                                               \
        _Pragma("unroll")                                                           \
        for (int i = 0; i < 4; i++) {                                               \
            int idx = tid + i * 256, r = idx >> 3, s = idx & 7;                     \
            cpasync16(sbase + (buf) * ASZ + (uint32_t)(r * (APAD * 2) + s * 16),    \
                      Ag + (size_t)r * KTOT + (c) * KC + s * 8);                    \
        }                                                                           \
        _Pragma("unroll")                                                           \
        for (int i = 0; i < 2; i++) {                                               \
            int idx = tid + i * 256, r = idx >> 3, s = idx & 7;                     \
            cpasync16(sbase + BBASE + (buf) * BSZ + (uint32_t)(r * (APAD * 2) + s * 16), \
                      Bg + (size_t)r * KTOT + (c) * KC + s * 8);                    \
        }                                                                           \
    }

    LOAD_CHUNK(0, 0); asm volatile("cp.async.commit_group;");
    LOAD_CHUNK(1, 1); asm volatile("cp.async.commit_group;");
    LOAD_CHUNK(2, 2); asm volatile("cp.async.commit_group;");

    for (int c = 0; c < NCHUNK; c++) {
        asm volatile("cp.async.wait_group 2;");
        __syncthreads();
        if (c + 3 < NCHUNK) LOAD_CHUNK(c + 3, (c + 3) & 3);
        asm volatile("cp.async.commit_group;");

        const int buf = c & 3;
        const uint32_t aB = sbase + buf * ASZ;
        const uint32_t bB = sbase + BBASE + buf * BSZ;
#pragma unroll
        for (int k16 = 0; k16 < 4; k16++) {
            uint32_t afr[2][4];
#pragma unroll
            for (int mt = 0; mt < 2; mt++) {
                int row = wm * 32 + mt * 16 + (lane & 15);
                uint32_t addr = aB + (uint32_t)(row * (APAD * 2) + ((lane >> 4) * 16) + k16 * 32);
                ldsm4(afr[mt], addr);
            }
            uint32_t bfr[4][2];
#pragma unroll
            for (int p = 0; p < 2; p++) {
                int row = wn * 32 + p * 16 + (lane & 7) + ((lane >> 4) * 8);
                uint32_t addr = bB + (uint32_t)(row * (APAD * 2) + (((lane >> 3) & 1) * 16) + k16 * 32);
                uint32_t t4[4];
                ldsm4(t4, addr);
                bfr[p * 2][0] = t4[0]; bfr[p * 2][1] = t4[1];
                bfr[p * 2 + 1][0] = t4[2]; bfr[p * 2 + 1][1] = t4[3];
            }
#pragma unroll
            for (int mt = 0; mt < 2; mt++)
#pragma unroll
                for (int nt = 0; nt < 4; nt++)
                    mma16816(acc[mt][nt], afr[mt], bfr[nt]);
        }
    }

#pragma unroll
    for (int mt = 0; mt < 2; mt++) {
#pragma unroll
        for (int nt = 0; nt < 4; nt++) {
            int row = bm + wm * 32 + mt * 16 + (lane >> 2);
            int col = bn + wn * 32 + nt * 8 + (lane & 3) * 2;
            float* p0 = g_logits + (size_t)row * NLOG + col;
            *(float2*)p0 = make_float2(acc[mt][nt][0], acc[mt][nt][1]);
            float* p1 = g_logits + (size_t)(row + 8) * NLOG + col;
            *(float2*)p1 = make_float2(acc[mt][nt][2], acc[mt][nt][3]);
        }
    }
#undef LOAD_CHUNK
}

// ---------------- kernel: fused step+scan soft-VM (issue-count-optimized) ----------------
// warp = one b (8 g x 4 q lanes); slog holds logits[256..805) pre-scaled by -log2(e)
// so each in-loop sigmoid is EX2(add)+RCP and each Gaussian is EX2(-p*p) in sqrt(log2e)
// coordinates.
__global__ __launch_bounds__(128) void scan_kernel() {
    __shared__ float slog[4][552];                 // -log2e * logits[256..805) per warp's b
    const int tid = threadIdx.x;
    const int warp = tid >> 5, lane = tid & 31;
    const int b = blockIdx.x * 4 + warp;
    const int g = lane >> 2, q = lane & 3;
    const float dg = (float)g * (2.f / 7.f) - 1.f;
    const float dgN = -dg * L2E;
    const int s0 = q * 8;

    {
        const int bb = blockIdx.x * 4;
        for (int i = tid; i < 4 * 552; i += 128) {
            int bl = i / 552, j = i - bl * 552;
            slog[bl][j] = (j < 549) ? -L2E * g_logits[(size_t)(bb + bl) * NLOG + 256 + j] : 0.f;
        }
    }
    __syncthreads();
    const float* sl = slog[warp];

    // R0: decode this lane's 8 register slots from logit bits [0..255] (one-time cost)
    const float* lr = g_logits + (size_t)b * NLOG + s0 * 8;
    float r[8], m[8];
#pragma unroll
    for (int j = 0; j < 8; j++) {
        float v = 0.f;
#pragma unroll
        for (int jb = 0; jb < 8; jb++)
            v += sigm(lr[j * 8 + jb] + dg) * (float)(1 << jb);
        r[j] = v; m[j] = 0.f;
    }

    // plen from scaled logits at local 544..548
    float pl = 0.f;
#pragma unroll
    for (int j = 0; j < 5; j++)
        pl += rcpf(1.f + ex2f(sl[544 + j] + dgN)) * (float)(1 << j);

    // role-dependent decode: q<3 -> dec5 at {64,224,384}+5t; q=3 -> op at 2t, weights {1,2,0,0,0}
    float wts[5];
#pragma unroll
    for (int j = 0; j < 5; j++) wts[j] = (q == 3) ? (j == 0 ? 1.f : (j == 1 ? 2.f : 0.f))
                                                  : (float)(1 << j);
    const int boff = (q == 3) ? 0 : (64 + q * 160);
    const int mult = (q == 3) ? 2 : 5;

    // slot coordinates scaled by sqrt(log2 e)
    float fis[8];
#pragma unroll
    for (int j = 0; j < 8; j++) fis[j] = (float)(s0 + j) * SQL;

    for (int t = 0; t < 32; t++) {
        const int ib = boff + mult * t;
        float dec = 0.f;
#pragma unroll
        for (int j = 0; j < 5; j++)
            dec += wts[j] * rcpf(1.f + ex2f(sl[ib + j] + dgN));

        float ow0 = 0.f, ow1 = 0.f, ow2 = 0.f, ow3 = 0.f;
        if (q == 3) {                              // op softmax on the q=3 lane only
            float ds = dec * SQL;
            float e0 = ex2f(-ds * ds);
            float p1 = ds - SQL;        float e1 = ex2f(-p1 * p1);
            float p2 = ds - 2.f * SQL;  float e2 = ex2f(-p2 * p2);
            float p3 = ds - 3.f * SQL;  float e3 = ex2f(-p3 * p3);
            float inv = rcpf(e0 + e1 + e2 + e3);
            ow0 = e0 * inv; ow1 = e1 * inv; ow2 = e2 * inv; ow3 = e3 * inv;
        }
        const int qb = lane & ~3;
        float dd = __shfl_sync(0xffffffffu, dec, qb);
        float d1 = __shfl_sync(0xffffffffu, dec, qb | 1);
        float d2 = __shfl_sync(0xffffffffu, dec, qb | 2);
        ow0 = __shfl_sync(0xffffffffu, ow0, qb | 3);
        ow1 = __shfl_sync(0xffffffffu, ow1, qb | 3);
        ow2 = __shfl_sync(0xffffffffu, ow2, qb | 3);
        ow3 = __shfl_sync(0xffffffffu, ow3, qb | 3);
        float act = sigm(pl - (float)t - 0.5f);

        const float dds = dd * SQL, d1s = d1 * SQL, d2s = d2 * SQL;
        float ed[8];
        float sd = 0.f, sa = 0.f, sb = 0.f;
        float dv = 0.f, v1 = 0.f, v2 = 0.f, lv = 0.f;
#pragma unroll
        for (int j = 0; j < 8; j++) {
            float pd = dds - fis[j]; float e_d = ex2f(-pd * pd);
            float pa = d1s - fis[j]; float e_1 = ex2f(-pa * pa);
            float pb = d2s - fis[j]; float e_2 = ex2f(-pb * pb);
            ed[j] = e_d;
            sd += e_d; sa += e_1; sb += e_2;
            dv += r[j] * e_d; v1 += r[j] * e_1; v2 += r[j] * e_2; lv += m[j] * e_1;
        }
#pragma unroll
        for (int off = 1; off <= 2; off <<= 1) {
            sd += __shfl_xor_sync(0xffffffffu, sd, off);
            sa += __shfl_xor_sync(0xffffffffu, sa, off);
            sb += __shfl_xor_sync(0xffffffffu, sb, off);
            dv += __shfl_xor_sync(0xffffffffu, dv, off);
            v1 += __shfl_xor_sync(0xffffffffu, v1, off);
            v2 += __shfl_xor_sync(0xffffffffu, v2, off);
            lv += __shfl_xor_sync(0xffffffffu, lv, off);
        }
        float inv_sd = rcpf(sd);
        float inv_sa = rcpf(sa);
        float inv_sb = rcpf(sb);
        dv *= inv_sd; v1 *= inv_sa; v2 *= inv_sb; lv *= inv_sa;

        float res = ow0 * (v1 + v2) + ow1 * (v1 - v2) + ow2 * lv + ow3 * dv;
        float grs = act * (ow0 + ow1 + ow2) * inv_sd;
        float gms = act * ow3 * inv_sd;
        float gr_res = grs * res, gm_v1 = gms * v1;
#pragma unroll
        for (int j = 0; j < 8; j++) {
            float w = ed[j];
            r[j] = fmaf(w, fmaf(-grs, r[j], gr_res), r[j]);
            m[j] = fmaf(w, fmaf(-gms, m[j], gm_v1), m[j]);
        }
    }
    const int bg = b * 8 + g;
    float* orow = g_Rf + (size_t)bg * 32 + s0;
    *(float4*)(orow)     = make_float4(r[0], r[1], r[2], r[3]);
    *(float4*)(orow + 4) = make_float4(r[4], r[5], r[6], r[7]);
}

// ---------------- kernel: h = Rf @ W_r2h^T + b, fused LayerNorm ----------------
__global__ __launch_bounds__(512) void final_kernel(const float* __restrict__ Wr,
                                                    const float* __restrict__ bias,
                                                    const float* __restrict__ lng,
                                                    const float* __restrict__ lnb,
                                                    float* __restrict__ out,
                                                    int rows_per_block) {
    const int c = threadIdx.x;
    const int lane = c & 31, warp = c >> 5;

    float w[32];
#pragma unroll
    for (int j = 0; j < 8; j++) {
        float4 v = *(const float4*)(Wr + (size_t)c * 32 + j * 4);
        w[4 * j] = v.x; w[4 * j + 1] = v.y; w[4 * j + 2] = v.z; w[4 * j + 3] = v.w;
    }
    const float bb = bias[c], gg = lng[c], be = lnb[c];

    __shared__ float srf[128];
    __shared__ float red[16][8];
    __shared__ float fin[8];

    const int row_base = blockIdx.x * rows_per_block;
    for (int batch = 0; batch < rows_per_block; batch += 4) {
        const int row0 = row_base + batch;
        __syncthreads();
        if (c < 128)
            srf[c] = g_Rf[(size_t)(row0 + (c & 3)) * 32 + (c >> 2)];
        __syncthreads();

        float a0 = 0.f, a1 = 0.f, a2 = 0.f, a3 = 0.f;
#pragma unroll
        for (int rIdx = 0; rIdx < 32; rIdx++) {
            float4 v = *(const float4*)&srf[rIdx * 4];
            float ww = w[rIdx];
            a0 += ww * v.x; a1 += ww * v.y; a2 += ww * v.z; a3 += ww * v.w;
        }
        float h[4] = {a0 + bb, a1 + bb, a2 + bb, a3 + bb};

        float s[8];
#pragma unroll
        for (int j = 0; j < 4; j++) { s[j] = h[j]; s[4 + j] = h[j] * h[j]; }
#pragma unroll
        for (int off = 16; off > 0; off >>= 1)
#pragma unroll
            for (int j = 0; j < 8; j++) s[j] += __shfl_xor_sync(0xffffffffu, s[j], off);
        if (lane == 0)
#pragma unroll
            for (int j = 0; j < 8; j++) red[warp][j] = s[j];
        __syncthreads();
        if (c < 8) {
            float tot = 0.f;
#pragma unroll
            for (int wi = 0; wi < 16; wi++) tot += red[wi][c];
            fin[c] = tot;
        }
        __syncthreads();
#pragma unroll
        for (int rr = 0; rr < 4; rr++) {
            float mu  = fin[rr] * (1.f / 512.f);
            float msq = fin[4 + rr] * (1.f / 512.f);
            float var = msq - mu * mu;
            float sc  = rsqrtf(var + 1e-5f);
            out[(size_t)(row0 + rr) * 512 + c] = (h[rr] - mu) * sc * gg + be;
        }
    }
}

// ---------------- launch ----------------
extern "C" void kernel_launch(void* const* d_in, const int* in_sizes, int n_in,
                              void* d_out, int out_size) {
    const float* z    = (const float*)d_in[0];
    const float* wR   = (const float*)d_in[1];
    const float* wOp  = (const float*)d_in[2];
    const float* wD   = (const float*)d_in[3];
    const float* wS1  = (const float*)d_in[4];
    const float* wS2  = (const float*)d_in[5];
    const float* wL   = (const float*)d_in[6];
    const float* wr2h = (const float*)d_in[7];
    const float* br2h = (const float*)d_in[8];
    const float* lng  = (const float*)d_in[9];
    const float* lnb  = (const float*)d_in[10];
    float* out = (float*)d_out;

    const int GEMM_SMEM = NBUF * (BM + BN) * APAD * 2;   // 110592 bytes
    cudaFuncSetAttribute(gemm_mma, cudaFuncAttributeMaxDynamicSharedMemorySize, GEMM_SMEM);

    const int PACK_TOTAL = ANUM + NLOG * KTOT;
    pack_ab_kernel<<<PACK_TOTAL / 256, 256>>>(z, wR, wOp, wD, wS1, wS2, wL);  // 1
    gemm_mma<<<dim3(NLOG / BN, B_ / BM), 256, GEMM_SMEM>>>();                 // 2
    scan_kernel<<<B_ / 4, 128>>>();                                           // 3
    final_kernel<<<1024, 512>>>(wr2h, br2h, lng, lnb, out, BG / 1024);        // 4 <- profiled
}

// round 16
// speedup vs baseline: 1.1083x; 1.0032x over previous
#include <cuda_runtime.h>
#include <cuda_bf16.h>
#include <cstdint>

#define B_   4096
#define HID  512
#define NR   32
#define T_   32
#define NLOG 832          // logit cols padded to 13*64 (805 meaningful)
#define BG   32768        // B_*G
#define KTOT 1536         // 3*512 split-bf16 stacking
#define BM   128
#define BN   64
#define KC   64
#define NCHUNK (KTOT / KC)   // 24
#define APAD 72              // smem row length in bf16 (144B, conflict-free ldmatrix)
#define NBUF 4
#define ANUM (B_ * KTOT)     // 6291456
#define L2E  1.4426950408889634f
#define SQL  1.2011224087864498f   // sqrt(log2 e)

// ---------------- scratch (device globals: no allocations allowed) ----------------
__device__ __nv_bfloat16 g_Ab[(size_t)B_ * KTOT];      // [m][k]  (hi,hi,lo)
__device__ __nv_bfloat16 g_Bb[(size_t)NLOG * KTOT];    // [n][k]  (hi,lo,hi)
__device__ float g_logits[(size_t)B_ * NLOG];          // z @ W_cat
__device__ float g_Rf[(size_t)BG * NR];                // [bg][r]

__device__ __forceinline__ float sigm(float x) {
    return __fdividef(1.f, 1.f + __expf(-x));
}
__device__ __forceinline__ float ex2f(float x) {
    float y; asm("ex2.approx.ftz.f32 %0, %1;" : "=f"(y) : "f"(x)); return y;
}
__device__ __forceinline__ float rcpf(float x) {
    float y; asm("rcp.approx.ftz.f32 %0, %1;" : "=f"(y) : "f"(x)); return y;
}

__device__ __forceinline__ uint32_t s2u(const void* p) {
    uint32_t a;
    asm("{ .reg .u64 t; cvta.to.shared.u64 t, %1; cvt.u32.u64 %0, t; }" : "=r"(a) : "l"(p));
    return a;
}
__device__ __forceinline__ void cpasync16(uint32_t saddr, const void* g) {
    asm volatile("cp.async.cg.shared.global [%0], [%1], 16;" :: "r"(saddr), "l"(g));
}
__device__ __forceinline__ void ldsm4(uint32_t* r, uint32_t addr) {
    asm volatile("ldmatrix.sync.aligned.m8n8.x4.shared.b16 {%0,%1,%2,%3}, [%4];"
                 : "=r"(r[0]), "=r"(r[1]), "=r"(r[2]), "=r"(r[3]) : "r"(addr));
}
__device__ __forceinline__ void mma16816(float* c, const uint32_t* a, const uint32_t* b) {
    asm volatile(
        "mma.sync.aligned.m16n8k16.row.col.f32.bf16.bf16.f32 "
        "{%0,%1,%2,%3}, {%4,%5,%6,%7}, {%8,%9}, {%0,%1,%2,%3};"
        : "+f"(c[0]), "+f"(c[1]), "+f"(c[2]), "+f"(c[3])
        : "r"(a[0]), "r"(a[1]), "r"(a[2]), "r"(a[3]), "r"(b[0]), "r"(b[1]));
}

// ---------------- kernel: fused pack of A and B (block-aligned split) ----------------
__global__ void pack_ab_kernel(const float* __restrict__ Z,
                               const float* __restrict__ wR,  const float* __restrict__ wOp,
                               const float* __restrict__ wD,  const float* __restrict__ wS1,
                               const float* __restrict__ wS2, const float* __restrict__ wL) {
    int idx = blockIdx.x * blockDim.x + threadIdx.x;
    if (idx < ANUM) {                     // A = [hi(z), hi(z), lo(z)], [m][k]
        int m = idx / KTOT, k = idx - m * KTOT;
        __nv_bfloat16 o;
        if (k < 1024) {
            o = __float2bfloat16(Z[(size_t)m * 512 + (k & 511)]);
        } else {
            float v = Z[(size_t)m * 512 + (k - 1024)];
            __nv_bfloat16 hi = __float2bfloat16(v);
            o = __float2bfloat16(v - __bfloat162float(hi));
        }
        g_Ab[idx] = o;
    } else {                              // B = [hi(W), lo(W), hi(W)], [n][k]
        idx -= ANUM;
        int n = idx / KTOT, k = idx - n * KTOT;
        int kr = (k < 1024) ? (k & 511) : (k - 1024);
        float v = 0.f;
        if      (n < 256) v = wR [kr * 256 + n];
        else if (n < 320) v = wOp[kr * 64  + (n - 256)];
        else if (n < 480) v = wD [kr * 160 + (n - 320)];
        else if (n < 640) v = wS1[kr * 160 + (n - 480)];
        else if (n < 800) v = wS2[kr * 160 + (n - 640)];
        else if (n < 805) v = wL [kr * 5   + (n - 800)];
        __nv_bfloat16 hi = __float2bfloat16(v);
        __nv_bfloat16 o;
        if (k < 512)       o = hi;
        else if (k < 1024) o = __float2bfloat16(v - __bfloat162float(hi));  // lo
        else               o = hi;
        g_Bb[idx] = o;
    }
}

// ---------------- kernel: mma.sync GEMM, 4-stage cp.async pipeline ----------------
__global__ __launch_bounds__(256) void gemm_mma() {
    extern __shared__ char sm[];
    const int tid  = threadIdx.x;
    const int lane = tid & 31, warp = tid >> 5;
    const int wm = warp & 3, wn = warp >> 2;
    const int bm = blockIdx.y * BM, bn = blockIdx.x * BN;

    const uint32_t ASZ = BM * APAD * 2;          // 18432
    const uint32_t BSZ = BN * APAD * 2;          // 9216
    const uint32_t BBASE = NBUF * ASZ;           // 73728
    const uint32_t sbase = s2u(sm);

    const __nv_bfloat16* Ag = g_Ab + (size_t)bm * KTOT;
    const __nv_bfloat16* Bg = g_Bb + (size_t)bn * KTOT;

    float acc[2][4][4];
#pragma unroll
    for (int mt = 0; mt < 2; mt++)
#pragma unroll
        for (int nt = 0; nt < 4; nt++)
#pragma unroll
            for (int j = 0; j < 4; j++) acc[mt][nt][j] = 0.f;

#define LOAD_CHUNK(c, buf)                                                          \
    {                                                                               \
        _Pragma("unroll")                                                           \
        for (int i = 0; i < 4; i++) {                                               \
            int idx = tid + i * 256, r = idx >> 3, s = idx & 7;                     \
            cpasync16(sbase + (buf) * ASZ + (uint32_t)(r * (APAD * 2) + s * 16),    \
                      Ag + (size_t)r * KTOT + (c) * KC + s * 8);                    \
        }                                                                           \
        _Pragma("unroll")                                                           \
        for (int i = 0; i < 2; i++) {                                               \
            int idx = tid + i * 256, r = idx >> 3, s = idx & 7;                     \
            cpasync16(sbase + BBASE + (buf) * BSZ + (uint32_t)(r * (APAD * 2) + s * 16), \
                      Bg + (size_t)r * KTOT + (c) * KC + s * 8);                    \
        }                                                                           \
    }

    LOAD_CHUNK(0, 0); asm volatile("cp.async.commit_group;");
    LOAD_CHUNK(1, 1); asm volatile("cp.async.commit_group;");
    LOAD_CHUNK(2, 2); asm volatile("cp.async.commit_group;");

    for (int c = 0; c < NCHUNK; c++) {
        asm volatile("cp.async.wait_group 2;");
        __syncthreads();
        if (c + 3 < NCHUNK) LOAD_CHUNK(c + 3, (c + 3) & 3);
        asm volatile("cp.async.commit_group;");

        const int buf = c & 3;
        const uint32_t aB = sbase + buf * ASZ;
        const uint32_t bB = sbase + BBASE + buf * BSZ;
#pragma unroll
        for (int k16 = 0; k16 < 4; k16++) {
            uint32_t afr[2][4];
#pragma unroll
            for (int mt = 0; mt < 2; mt++) {
                int row = wm * 32 + mt * 16 + (lane & 15);
                uint32_t addr = aB + (uint32_t)(row * (APAD * 2) + ((lane >> 4) * 16) + k16 * 32);
                ldsm4(afr[mt], addr);
            }
            uint32_t bfr[4][2];
#pragma unroll
            for (int p = 0; p < 2; p++) {
                int row = wn * 32 + p * 16 + (lane & 7) + ((lane >> 4) * 8);
                uint32_t addr = bB + (uint32_t)(row * (APAD * 2) + (((lane >> 3) & 1) * 16) + k16 * 32);
                uint32_t t4[4];
                ldsm4(t4, addr);
                bfr[p * 2][0] = t4[0]; bfr[p * 2][1] = t4[1];
                bfr[p * 2 + 1][0] = t4[2]; bfr[p * 2 + 1][1] = t4[3];
            }
#pragma unroll
            for (int mt = 0; mt < 2; mt++)
#pragma unroll
                for (int nt = 0; nt < 4; nt++)
                    mma16816(acc[mt][nt], afr[mt], bfr[nt]);
        }
    }

#pragma unroll
    for (int mt = 0; mt < 2; mt++) {
#pragma unroll
        for (int nt = 0; nt < 4; nt++) {
            int row = bm + wm * 32 + mt * 16 + (lane >> 2);
            int col = bn + wn * 32 + nt * 8 + (lane & 3) * 2;
            float* p0 = g_logits + (size_t)row * NLOG + col;
            *(float2*)p0 = make_float2(acc[mt][nt][0], acc[mt][nt][1]);
            float* p1 = g_logits + (size_t)(row + 8) * NLOG + col;
            *(float2*)p1 = make_float2(acc[mt][nt][2], acc[mt][nt][3]);
        }
    }
#undef LOAD_CHUNK
}

// ---------------- kernel: fused step+scan soft-VM (issue-count-optimized) ----------------
// warp = one b (8 g x 4 q lanes); slog holds logits[256..805) pre-scaled by -log2(e)
// so each in-loop sigmoid is EX2(add)+RCP and each Gaussian is EX2(-p*p) in sqrt(log2e)
// coordinates.
__global__ __launch_bounds__(128) void scan_kernel() {
    __shared__ float slog[4][552];                 // -log2e * logits[256..805) per warp's b
    const int tid = threadIdx.x;
    const int warp = tid >> 5, lane = tid & 31;
    const int b = blockIdx.x * 4 + warp;
    const int g = lane >> 2, q = lane & 3;
    const float dg = (float)g * (2.f / 7.f) - 1.f;
    const float dgN = -dg * L2E;
    const int s0 = q * 8;

    {
        const int bb = blockIdx.x * 4;
        for (int i = tid; i < 4 * 552; i += 128) {
            int bl = i / 552, j = i - bl * 552;
            slog[bl][j] = (j < 549) ? -L2E * g_logits[(size_t)(bb + bl) * NLOG + 256 + j] : 0.f;
        }
    }
    __syncthreads();
    const float* sl = slog[warp];

    // R0: decode this lane's 8 register slots from logit bits [0..255] (one-time cost)
    const float* lr = g_logits + (size_t)b * NLOG + s0 * 8;
    float r[8], m[8];
#pragma unroll
    for (int j = 0; j < 8; j++) {
        float v = 0.f;
#pragma unroll
        for (int jb = 0; jb < 8; jb++)
            v += sigm(lr[j * 8 + jb] + dg) * (float)(1 << jb);
        r[j] = v; m[j] = 0.f;
    }

    // plen from scaled logits at local 544..548
    float pl = 0.f;
#pragma unroll
    for (int j = 0; j < 5; j++)
        pl += rcpf(1.f + ex2f(sl[544 + j] + dgN)) * (float)(1 << j);

    // role-dependent decode: q<3 -> dec5 at {64,224,384}+5t; q=3 -> op at 2t, weights {1,2,0,0,0}
    float wts[5];
#pragma unroll
    for (int j = 0; j < 5; j++) wts[j] = (q == 3) ? (j == 0 ? 1.f : (j == 1 ? 2.f : 0.f))
                                                  : (float)(1 << j);
    const int boff = (q == 3) ? 0 : (64 + q * 160);
    const int mult = (q == 3) ? 2 : 5;

    // slot coordinates scaled by sqrt(log2 e)
    float fis[8];
#pragma unroll
    for (int j = 0; j < 8; j++) fis[j] = (float)(s0 + j) * SQL;

    for (int t = 0; t < 32; t++) {
        const int ib = boff + mult * t;
        float dec = 0.f;
#pragma unroll
        for (int j = 0; j < 5; j++)
            dec += wts[j] * rcpf(1.f + ex2f(sl[ib + j] + dgN));

        float ow0 = 0.f, ow1 = 0.f, ow2 = 0.f, ow3 = 0.f;
        if (q == 3) {                              // op softmax on the q=3 lane only
            float ds = dec * SQL;
            float e0 = ex2f(-ds * ds);
            float p1 = ds - SQL;        float e1 = ex2f(-p1 * p1);
            float p2 = ds - 2.f * SQL;  float e2 = ex2f(-p2 * p2);
            float p3 = ds - 3.f * SQL;  float e3 = ex2f(-p3 * p3);
            float inv = rcpf(e0 + e1 + e2 + e3);
            ow0 = e0 * inv; ow1 = e1 * inv; ow2 = e2 * inv; ow3 = e3 * inv;
        }
        const int qb = lane & ~3;
        float dd = __shfl_sync(0xffffffffu, dec, qb);
        float d1 = __shfl_sync(0xffffffffu, dec, qb | 1);
        float d2 = __shfl_sync(0xffffffffu, dec, qb | 2);
        ow0 = __shfl_sync(0xffffffffu, ow0, qb | 3);
        ow1 = __shfl_sync(0xffffffffu, ow1, qb | 3);
        ow2 = __shfl_sync(0xffffffffu, ow2, qb | 3);
        ow3 = __shfl_sync(0xffffffffu, ow3, qb | 3);
        float act = sigm(pl - (float)t - 0.5f);

        const float dds = dd * SQL, d1s = d1 * SQL, d2s = d2 * SQL;
        float ed[8];
        float sd = 0.f, sa = 0.f, sb = 0.f;
        float dv = 0.f, v1 = 0.f, v2 = 0.f, lv = 0.f;
#pragma unroll
        for (int j = 0; j < 8; j++) {
            float pd = dds - fis[j]; float e_d = ex2f(-pd * pd);
            float pa = d1s - fis[j]; float e_1 = ex2f(-pa * pa);
            float pb = d2s - fis[j]; float e_2 = ex2f(-pb * pb);
            ed[j] = e_d;
            sd += e_d; sa += e_1; sb += e_2;
            dv += r[j] * e_d; v1 += r[j] * e_1; v2 += r[j] * e_2; lv += m[j] * e_1;
        }
#pragma unroll
        for (int off = 1; off <= 2; off <<= 1) {
            sd += __shfl_xor_sync(0xffffffffu, sd, off);
            sa += __shfl_xor_sync(0xffffffffu, sa, off);
            sb += __shfl_xor_sync(0xffffffffu, sb, off);
            dv += __shfl_xor_sync(0xffffffffu, dv, off);
            v1 += __shfl_xor_sync(0xffffffffu, v1, off);
            v2 += __shfl_xor_sync(0xffffffffu, v2, off);
            lv += __shfl_xor_sync(0xffffffffu, lv, off);
        }
        float inv_sd = rcpf(sd);
        float inv_sa = rcpf(sa);
        float inv_sb = rcpf(sb);
        dv *= inv_sd; v1 *= inv_sa; v2 *= inv_sb; lv *= inv_sa;

        float res = ow0 * (v1 + v2) + ow1 * (v1 - v2) + ow2 * lv + ow3 * dv;
        float grs = act * (ow0 + ow1 + ow2) * inv_sd;
        float gms = act * ow3 * inv_sd;
        float gr_res = grs * res, gm_v1 = gms * v1;
#pragma unroll
        for (int j = 0; j < 8; j++) {
            float w = ed[j];
            r[j] = fmaf(w, fmaf(-grs, r[j], gr_res), r[j]);
            m[j] = fmaf(w, fmaf(-gms, m[j], gm_v1), m[j]);
        }
    }
    const int bg = b * 8 + g;
    float* orow = g_Rf + (size_t)bg * 32 + s0;
    *(float4*)(orow)     = make_float4(r[0], r[1], r[2], r[3]);
    *(float4*)(orow + 4) = make_float4(r[4], r[5], r[6], r[7]);
}

// ---------------- kernel: h = Rf @ W_r2h^T + b, fused LayerNorm ----------------
__global__ __launch_bounds__(512) void final_kernel(const float* __restrict__ Wr,
                                                    const float* __restrict__ bias,
                                                    const float* __restrict__ lng,
                                                    const float* __restrict__ lnb,
                                                    float* __restrict__ out,
                                                    int rows_per_block) {
    const int c = threadIdx.x;
    const int lane = c & 31, warp = c >> 5;

    float w[32];
#pragma unroll
    for (int j = 0; j < 8; j++) {
        float4 v = *(const float4*)(Wr + (size_t)c * 32 + j * 4);
        w[4 * j] = v.x; w[4 * j + 1] = v.y; w[4 * j + 2] = v.z; w[4 * j + 3] = v.w;
    }
    const float bb = bias[c], gg = lng[c], be = lnb[c];

    __shared__ float srf[128];
    __shared__ float red[16][8];
    __shared__ float fin[8];

    const int row_base = blockIdx.x * rows_per_block;
    for (int batch = 0; batch < rows_per_block; batch += 4) {
        const int row0 = row_base + batch;
        __syncthreads();
        if (c < 128)
            srf[c] = g_Rf[(size_t)(row0 + (c & 3)) * 32 + (c >> 2)];
        __syncthreads();

        float a0 = 0.f, a1 = 0.f, a2 = 0.f, a3 = 0.f;
#pragma unroll
        for (int rIdx = 0; rIdx < 32; rIdx++) {
            float4 v = *(const float4*)&srf[rIdx * 4];
            float ww = w[rIdx];
            a0 += ww * v.x; a1 += ww * v.y; a2 += ww * v.z; a3 += ww * v.w;
        }
        float h[4] = {a0 + bb, a1 + bb, a2 + bb, a3 + bb};

        float s[8];
#pragma unroll
        for (int j = 0; j < 4; j++) { s[j] = h[j]; s[4 + j] = h[j] * h[j]; }
#pragma unroll
        for (int off = 16; off > 0; off >>= 1)
#pragma unroll
            for (int j = 0; j < 8; j++) s[j] += __shfl_xor_sync(0xffffffffu, s[j], off);
        if (lane == 0)
#pragma unroll
            for (int j = 0; j < 8; j++) red[warp][j] = s[j];
        __syncthreads();
        if (c < 8) {
            float tot = 0.f;
#pragma unroll
            for (int wi = 0; wi < 16; wi++) tot += red[wi][c];
            fin[c] = tot;
        }
        __syncthreads();
#pragma unroll
        for (int rr = 0; rr < 4; rr++) {
            float mu  = fin[rr] * (1.f / 512.f);
            float msq = fin[4 + rr] * (1.f / 512.f);
            float var = msq - mu * mu;
            float sc  = rsqrtf(var + 1e-5f);
            out[(size_t)(row0 + rr) * 512 + c] = (h[rr] - mu) * sc * gg + be;
        }
    }
}

// ---------------- launch ----------------
extern "C" void kernel_launch(void* const* d_in, const int* in_sizes, int n_in,
                              void* d_out, int out_size) {
    const float* z    = (const float*)d_in[0];
    const float* wR   = (const float*)d_in[1];
    const float* wOp  = (const float*)d_in[2];
    const float* wD   = (const float*)d_in[3];
    const float* wS1  = (const float*)d_in[4];
    const float* wS2  = (const float*)d_in[5];
    const float* wL   = (const float*)d_in[6];
    const float* wr2h = (const float*)d_in[7];
    const float* br2h = (const float*)d_in[8];
    const float* lng  = (const float*)d_in[9];
    const float* lnb  = (const float*)d_in[10];
    float* out = (float*)d_out;

    const int GEMM_SMEM = NBUF * (BM + BN) * APAD * 2;   // 110592 bytes
    cudaFuncSetAttribute(gemm_mma, cudaFuncAttributeMaxDynamicSharedMemorySize, GEMM_SMEM);

    const int PACK_TOTAL = ANUM + NLOG * KTOT;
    pack_ab_kernel<<<PACK_TOTAL / 256, 256>>>(z, wR, wOp, wD, wS1, wS2, wL);  // 1
    gemm_mma<<<dim3(NLOG / BN, B_ / BM), 256, GEMM_SMEM>>>();                 // 2
    scan_kernel<<<B_ / 4, 128>>>();                                           // 3
    final_kernel<<<1024, 512>>>(wr2h, br2h, lng, lnb, out, BG / 1024);        // 4 <- profiled
}